// round 8
// baseline (speedup 1.0000x reference)
#include <cuda_runtime.h>
#include <cuda_bf16.h>
#include <math.h>
#include <stdint.h>

#define TT   512
#define BB   64
#define DD   1024
#define NBK  16
#define TOKN (TT*BB)                 // 32768
#define CAP  8192
#define NLIST (NBK*CAP)
#define OUT_OFF ((size_t)TOKN*64)
#define NKTI (DD/16)                 // 64 k-stages of 16

// ---------------- scratch ---------------------------------------------------
__device__ float    g_q[(size_t)TOKN*64];
__device__ float    g_w[TOKN*NBK];
__device__ int      g_sel[TOKN*2];
__device__ float    g_selout[(size_t)TOKN*2*192];
__device__ float    g_part4[(size_t)TOKN*4*64];      // 33.5 MB (L2-resident)
__device__ unsigned g_list[NLIST];
__device__ int      g_cursor[NBK];
// W prepack (12.6 MB): unit (row R, kti, j) = (h_b0, h_b1, l_b0, l_b1)
__device__ uint4    g_wpack[(size_t)NBK*192*256];

// ---------------- fast math --------------------------------------------------
__device__ __forceinline__ float ex2a(float x){ float r; asm("ex2.approx.f32 %0,%1;":"=f"(r):"f"(x)); return r; }
__device__ __forceinline__ float rcpa(float x){ float r; asm("rcp.approx.f32 %0,%1;":"=f"(r):"f"(x)); return r; }
__device__ __forceinline__ float fast_rcp(float z){ float y = rcpa(z); return y * fmaf(-z, y, 2.0f); }
__device__ __forceinline__ float fsig(float x){ float E = ex2a(-1.44269504f * x); return fast_rcp(1.0f + E); }
__device__ __forceinline__ float ftanh(float x){ float E = ex2a(2.88539008f * x); return fmaf(-2.0f, fast_rcp(1.0f + E), 1.0f); }

__device__ __forceinline__ uint32_t f2tf(float f){ uint32_t r; asm("cvt.rna.tf32.f32 %0,%1;":"=r"(r):"f"(f)); return r; }
__device__ __forceinline__ uint32_t bf16r(float f){ uint16_t r; asm("cvt.rn.bf16.f32 %0,%1;":"=h"(r):"f"(f)); return (uint32_t)r; }
__device__ __forceinline__ void split_pack(float a, float b, uint32_t &hi, uint32_t &lo){
    uint32_t ha = bf16r(a), hb = bf16r(b);
    float ra = a - __uint_as_float(ha << 16);
    float rb = b - __uint_as_float(hb << 16);
    hi = ha | (hb << 16);
    lo = bf16r(ra) | (bf16r(rb) << 16);
}

__device__ __forceinline__ void mma_tf32(float4 &d, const uint4 &a, const uint2 &b){
    asm volatile("mma.sync.aligned.m16n8k8.row.col.f32.tf32.tf32.f32 "
                 "{%0,%1,%2,%3},{%4,%5,%6,%7},{%8,%9},{%0,%1,%2,%3};"
                 : "+f"(d.x), "+f"(d.y), "+f"(d.z), "+f"(d.w)
                 : "r"(a.x), "r"(a.y), "r"(a.z), "r"(a.w), "r"(b.x), "r"(b.y));
}
__device__ __forceinline__ void mma_bf16(float4 &d, uint32_t a0, uint32_t a1, uint32_t a2, uint32_t a3,
                                         uint32_t b0, uint32_t b1){
    asm volatile("mma.sync.aligned.m16n8k16.row.col.f32.bf16.bf16.f32 "
                 "{%0,%1,%2,%3},{%4,%5,%6,%7},{%8,%9},{%0,%1,%2,%3};"
                 : "+f"(d.x), "+f"(d.y), "+f"(d.z), "+f"(d.w)
                 : "r"(a0), "r"(a1), "r"(a2), "r"(a3), "r"(b0), "r"(b1));
}

__device__ __forceinline__ void cpa16(uint32_t dst, const void* src){
    asm volatile("cp.async.cg.shared.global [%0], [%1], 16;\n" :: "r"(dst), "l"(src));
}
__device__ __forceinline__ void cpa_commit(){ asm volatile("cp.async.commit_group;\n"); }
template<int N> __device__ __forceinline__ void cpa_wait(){ asm volatile("cp.async.wait_group %0;\n"::"n"(N)); }

// ---------------- K0: prep — W split-pack + list init ------------------------
__global__ __launch_bounds__(256) void k_prep(const float* __restrict__ Wkv,
                                              const float* __restrict__ Wbeta) {
    const int bid = blockIdx.x, tid = threadIdx.x;
    if (bid < NBK * 192) {
        const int kti = tid >> 2, j = tid & 3;
        int e = bid / 192, n = bid % 192;
        const float* base = (n < 128) ? (Wkv + ((size_t)e * 128 + n) * DD)
                                      : (Wbeta + ((size_t)e * 64 + (n - 128)) * DD);
        const float* src = base + kti * 16 + 2 * j;
        float2 v0 = *(const float2*)src;
        float2 v1 = *(const float2*)(src + 8);
        uint32_t h0, l0, h1, l1;
        split_pack(v0.x, v0.y, h0, l0);
        split_pack(v1.x, v1.y, h1, l1);
        g_wpack[(size_t)bid * 256 + tid] = make_uint4(h0, h1, l0, l1);
    } else {
        int i = (bid - NBK * 192) * 256 + tid;
        if (i < NLIST) g_list[i] = 0xFFFFFFFFu;
        if (i < NBK)   g_cursor[i] = i * CAP;
    }
}

// ---------------- K1: router+q GEMM (tf32 3-split) + fused top-k/fill --------
__global__ __launch_bounds__(256) void k_rq_mma(const float* __restrict__ x,
                                                const float* __restrict__ Wr,
                                                const float* __restrict__ Wq) {
    __shared__ uint32_t Ah[4*2*32*4], Al[4*2*32*4];
    __shared__ uint32_t Bh[10*2*32*2], Bl[10*2*32*2];
    __shared__ float slog[64][20];

    const int tid = threadIdx.x;
    const int row0 = blockIdx.x * 64;
    const int warp = tid >> 5, lane = tid & 31;
    const int wm = warp >> 1, wn = warp & 1;

    float4 acc[5];
#pragma unroll
    for (int j = 0; j < 5; j++) acc[j] = make_float4(0.f, 0.f, 0.f, 0.f);

    const int xrow = tid >> 2, xk0 = (tid & 3) * 4;
    const float* xp = x + (size_t)(row0 + xrow) * DD + xk0;
    const int xs = xk0 >> 3;
    const int xreg = ((xk0 & 4) ? 2 : 0) + (((xrow & 15) >= 8) ? 1 : 0);
    const int xbase = ((((xrow >> 4) * 2 + xs) * 32 + ((xrow & 7) << 2)) << 2) + xreg;

    for (int kt = 0; kt < DD; kt += 16) {
        {
            float4 v = *(const float4*)(xp + kt);
            float vv[4] = {v.x, v.y, v.z, v.w};
#pragma unroll
            for (int j = 0; j < 4; j++) {
                uint32_t h = f2tf(vv[j]);
                Ah[xbase + (j << 2)] = h;
                Al[xbase + (j << 2)] = f2tf(vv[j] - __uint_as_float(h));
            }
        }
#pragma unroll
        for (int it = 0; it < 2; it++) {
            int fi = tid + it * 256;
            if (fi < 320) {
                int row = fi >> 2, k0 = (fi & 3) * 4;
                const float* wp = (row < 16) ? (Wr + (size_t)row * DD)
                                             : (Wq + (size_t)(row - 16) * DD);
                float4 v = *(const float4*)(wp + kt + k0);
                int s = k0 >> 3, reg = (k0 & 4) ? 1 : 0;
                int base = ((((row >> 3) * 2 + s) * 32 + ((row & 7) << 2)) << 1) + reg;
                float vv[4] = {v.x, v.y, v.z, v.w};
#pragma unroll
                for (int j = 0; j < 4; j++) {
                    uint32_t h = f2tf(vv[j]);
                    Bh[base + (j << 1)] = h;
                    Bl[base + (j << 1)] = f2tf(vv[j] - __uint_as_float(h));
                }
            }
        }
        __syncthreads();
#pragma unroll
        for (int s = 0; s < 2; s++) {
            int aidx = (((wm * 2 + s) * 32 + lane) << 2);
            uint4 ah = *(const uint4*)&Ah[aidx];
            uint4 al = *(const uint4*)&Al[aidx];
#pragma unroll
            for (int ni = 0; ni < 5; ni++) {
                int bidx = ((((wn * 5 + ni) * 2 + s) * 32 + lane) << 1);
                uint2 bh = *(const uint2*)&Bh[bidx];
                uint2 bl = *(const uint2*)&Bl[bidx];
                mma_tf32(acc[ni], ah, bh);
                mma_tf32(acc[ni], ah, bl);
                mma_tf32(acc[ni], al, bh);
            }
        }
        __syncthreads();
    }
    // epilogue: logits -> smem, q -> global
    int rloc = wm * 16 + (lane >> 2);
    int r0 = row0 + rloc;
#pragma unroll
    for (int ni = 0; ni < 5; ni++) {
        int c0 = wn * 40 + ni * 8 + ((lane & 3) << 1);
        if (c0 < 16) {
            slog[rloc][c0]     = acc[ni].x; slog[rloc][c0 + 1]     = acc[ni].y;
            slog[rloc + 8][c0] = acc[ni].z; slog[rloc + 8][c0 + 1] = acc[ni].w;
        } else {
            int c = c0 - 16;
            *(float2*)&g_q[(size_t)r0 * 64 + c]       = make_float2(acc[ni].x, acc[ni].y);
            *(float2*)&g_q[(size_t)(r0 + 8) * 64 + c] = make_float2(acc[ni].z, acc[ni].w);
        }
    }
    __syncthreads();
    // fused top-2 + softmax + list fill (one thread per token)
    if (tid < 64) {
        int tok = row0 + tid;
        float lg[16];
#pragma unroll
        for (int c = 0; c < 16; c++) lg[c] = slog[tid][c];
        float v0 = -1e30f, v1 = -1e30f; int i0 = 0, i1 = 0;
#pragma unroll
        for (int c = 0; c < 16; c++) {
            float l = lg[c];
            if (l > v0) { v1 = v0; i1 = i0; v0 = l; i0 = c; }
            else if (l > v1) { v1 = l; i1 = c; }
        }
        float s = 0.0f, w[16];
#pragma unroll
        for (int c = 0; c < 16; c++) { float e = __expf(lg[c] - v0); w[c] = e; s += e; }
        float rs = 1.0f / s;
#pragma unroll
        for (int c = 0; c < 16; c++) g_w[(size_t)tok * 16 + c] = w[c] * rs;
        g_sel[tok * 2 + 0] = i0;
        g_sel[tok * 2 + 1] = i1;
        int p0 = atomicAdd(&g_cursor[i0], 1); g_list[p0] = (unsigned)(tok * 2);
        int p1 = atomicAdd(&g_cursor[i1], 1); g_list[p1] = (unsigned)(tok * 2 + 1);
    }
}

// ---------------- K2: grouped bf16 3-split GEMM (R6 layout, unchanged) -------
__global__ __launch_bounds__(256, 2) void k_ggemm(const float* __restrict__ x) {
    __shared__ __align__(16) uint4 SMA[2][4 * 2 * 32];
    __shared__ __align__(16) uint4 SMB[2][24 * 32];
    __shared__ unsigned s_ent[64];

    const int tid = threadIdx.x;
    const int e = blockIdx.x >> 7;
    const int lofs = e * CAP + (blockIdx.x & 127) * 64;
    if (tid < 64) s_ent[tid] = g_list[lofs + tid];
    __syncthreads();
    if (s_ent[0] == 0xFFFFFFFFu) return;

    const int warp = tid >> 5, lane = tid & 31;
    const int wm = warp >> 2, wn = warp & 3;

    const int a_mt = tid >> 6, a_rlow = (tid >> 3) & 7, a_j = tid & 7;
    const int a_lane = a_rlow * 4 + (a_j & 3);
    const int a_reg  = (a_j >= 4) ? 2 : 0;
    const float* a_p0;
    const float* a_p1;
    {
        unsigned e0 = s_ent[a_mt * 16 + a_rlow];
        unsigned e1 = s_ent[a_mt * 16 + a_rlow + 8];
        a_p0 = (e0 != 0xFFFFFFFFu) ? (x + (size_t)(e0 >> 1) * DD + 2 * a_j) : nullptr;
        a_p1 = (e1 != 0xFFFFFFFFu) ? (x + (size_t)(e1 >> 1) * DD + 2 * a_j) : nullptr;
    }
    uint32_t a_hi_addr = (uint32_t)__cvta_generic_to_shared(
        &((uint32_t*)&SMA[0][(a_mt * 2 + 0) * 32 + a_lane])[a_reg]);
    uint32_t a_lo_addr = (uint32_t)__cvta_generic_to_shared(
        &((uint32_t*)&SMA[0][(a_mt * 2 + 1) * 32 + a_lane])[a_reg]);

    const uint4* b_src[3];
    uint32_t b_dst[3];
#pragma unroll
    for (int i = 0; i < 3; i++) {
        int u = tid + i * 256;
        int n = u >> 2, j = u & 3;
        b_src[i] = &g_wpack[((size_t)e * 192 + n) * 256 + j];
        b_dst[i] = (uint32_t)__cvta_generic_to_shared(&SMB[0][(n >> 3) * 32 + (n & 7) * 4 + j]);
    }

    float4 acc[2][6];
#pragma unroll
    for (int i = 0; i < 2; i++)
#pragma unroll
        for (int j = 0; j < 6; j++) acc[i][j] = make_float4(0.f, 0.f, 0.f, 0.f);

    {
        float2 v0 = make_float2(0.f, 0.f), v1 = v0;
        if (a_p0) v0 = *(const float2*)a_p0;
        if (a_p1) v1 = *(const float2*)a_p1;
        uint32_t h0, l0, h1, l1;
        split_pack(v0.x, v0.y, h0, l0);
        split_pack(v1.x, v1.y, h1, l1);
        asm volatile("st.shared.v2.u32 [%0], {%1,%2};" :: "r"(a_hi_addr), "r"(h0), "r"(h1));
        asm volatile("st.shared.v2.u32 [%0], {%1,%2};" :: "r"(a_lo_addr), "r"(l0), "r"(l1));
#pragma unroll
        for (int i = 0; i < 3; i++) cpa16(b_dst[i], b_src[i]);
        cpa_commit();
    }

    const uint32_t ABUF = sizeof(uint4) * 4 * 2 * 32;
    const uint32_t BBUF = sizeof(uint4) * 24 * 32;

    for (int kts = 0; kts < NKTI; kts++) {
        const int buf = kts & 1;
        float2 va0 = make_float2(0.f, 0.f), va1 = va0;
        const bool more = (kts + 1 < NKTI);
        if (more) {
            if (a_p0) va0 = *(const float2*)(a_p0 + (kts + 1) * 16);
            if (a_p1) va1 = *(const float2*)(a_p1 + (kts + 1) * 16);
        }
        cpa_wait<0>();
        __syncthreads();
        if (more) {
            uint32_t bo = (buf ^ 1) * BBUF;
#pragma unroll
            for (int i = 0; i < 3; i++) cpa16(b_dst[i] + bo, b_src[i] + (size_t)(kts + 1) * 4);
            cpa_commit();
        }
        {
            const uint4* A0 = SMA[buf];
            const uint4* B0 = SMB[buf];
            uint4 qa_h[2], qa_l[2];
#pragma unroll
            for (int mi = 0; mi < 2; mi++) {
                int mt = wm * 2 + mi;
                qa_h[mi] = A0[(mt * 2 + 0) * 32 + lane];
                qa_l[mi] = A0[(mt * 2 + 1) * 32 + lane];
            }
#pragma unroll
            for (int ni = 0; ni < 6; ni++) {
                uint4 qb = B0[(wn * 6 + ni) * 32 + lane];
#pragma unroll
                for (int mi = 0; mi < 2; mi++) {
                    float4 &d = acc[mi][ni];
                    mma_bf16(d, qa_h[mi].x, qa_h[mi].y, qa_h[mi].z, qa_h[mi].w, qb.x, qb.y);
                    mma_bf16(d, qa_h[mi].x, qa_h[mi].y, qa_h[mi].z, qa_h[mi].w, qb.z, qb.w);
                    mma_bf16(d, qa_l[mi].x, qa_l[mi].y, qa_l[mi].z, qa_l[mi].w, qb.x, qb.y);
                }
            }
        }
        if (more) {
            uint32_t h0, l0, h1, l1;
            split_pack(va0.x, va0.y, h0, l0);
            split_pack(va1.x, va1.y, h1, l1);
            uint32_t ao = (buf ^ 1) * ABUF;
            asm volatile("st.shared.v2.u32 [%0], {%1,%2};" :: "r"(a_hi_addr + ao), "r"(h0), "r"(h1));
            asm volatile("st.shared.v2.u32 [%0], {%1,%2};" :: "r"(a_lo_addr + ao), "r"(l0), "r"(l1));
        }
    }

#pragma unroll
    for (int mi = 0; mi < 2; mi++) {
        int r0 = (wm * 2 + mi) * 16 + (lane >> 2);
        unsigned e0 = s_ent[r0], e1 = s_ent[r0 + 8];
#pragma unroll
        for (int ni = 0; ni < 6; ni++) {
            int c0 = wn * 48 + ni * 8 + ((lane & 3) << 1);
            if (e0 != 0xFFFFFFFFu)
                *(float2*)&g_selout[(size_t)e0 * 192 + c0] = make_float2(acc[mi][ni].x, acc[mi][ni].y);
            if (e1 != 0xFFFFFFFFu)
                *(float2*)&g_selout[(size_t)e1 * 192 + c0] = make_float2(acc[mi][ni].z, acc[mi][ni].w);
        }
    }
}

// ---------------- K3: recurrent scan, CTA = (batch, c-group of 4) ------------
// 256 CTAs x 256 threads; thread (cl, i) owns S row i of block c = cg*4+cl.
__global__ __launch_bounds__(256) void k_scan(const float* __restrict__ b_beta,
                                              float* __restrict__ out) {
    const int b  = blockIdx.x >> 2;
    const int cg = blockIdx.x & 3;
    const int tid = threadIdx.x;
    const int cl = tid >> 6, i = tid & 63;
    const int c  = cg * 4 + cl;

    float S[64];
#pragma unroll
    for (int j = 0; j < 64; j++) S[j] = 0.0f;
    const float bb = b_beta[c * 64 + i];

    __shared__ float sq[2][64];
    __shared__ float sk[4][64];
    __shared__ float sbo[4][64];

    for (int t = 0; t < TT; t++) {
        const int tok = t * BB + b;
        const int p = t & 1;
        if (tid < 64) sq[p][tid] = g_q[(size_t)tok * 64 + tid];
        const int2 sel = *(const int2*)&g_sel[tok * 2];
        const float wv = g_w[(size_t)tok * 16 + c];
        const int slot = (sel.x == c) ? 0 : ((sel.y == c) ? 1 : -1);
        float kk = 0.f, vv = 0.f, bp = 0.f;
        if (slot >= 0) {
            const float* pp = g_selout + ((size_t)tok * 2 + slot) * 192;
            kk = pp[i]; vv = pp[64 + i]; bp = pp[128 + i];
        }
        sk[cl][i] = kk;
        __syncthreads();                       // barrier 1: sq + sk visible

        if (slot >= 0) {                       // uniform per 2-warp group
            float k1 = sk[cl][i ^ 32];
            float ps = fmaf(kk, kk, k1 * k1);
#pragma unroll
            for (int o = 16; o; o >>= 1) ps += __shfl_xor_sync(0xffffffffu, ps, o);
            float rn = fast_rcp(sqrtf(ps) + 1e-6f);
            const float* kr = sk[cl];
            float r0 = 0.f, r1 = 0.f, r2 = 0.f, r3 = 0.f;
#pragma unroll
            for (int j = 0; j < 64; j += 4) {
                r0 = fmaf(S[j+0], kr[j+0], r0);
                r1 = fmaf(S[j+1], kr[j+1], r1);
                r2 = fmaf(S[j+2], kr[j+2], r2);
                r3 = fmaf(S[j+3], kr[j+3], r3);
            }
            float delta = vv - ((r0 + r1) + (r2 + r3)) * rn;
            float beta = fsig(bp + bb);
            float sc = delta * rn;
#pragma unroll
            for (int j = 0; j < 64; j++)
                S[j] = ftanh(fmaf(beta, S[j], sc * kr[j]));
        }
        const float* q = sq[p];
        float a0 = 0.f, a1 = 0.f, a2 = 0.f, a3 = 0.f;
#pragma unroll
        for (int j = 0; j < 64; j += 4) {
            a0 = fmaf(S[j+0], q[j+0], a0);
            a1 = fmaf(S[j+1], q[j+1], a1);
            a2 = fmaf(S[j+2], q[j+2], a2);
            a3 = fmaf(S[j+3], q[j+3], a3);
        }
        float sv = (a0 + a1) + (a2 + a3);
        sbo[cl][i] = wv * sv * sv * fsig(sv);
        __syncthreads();                       // barrier 2: sbo visible
        if (tid < 64) {
            float s = sbo[0][tid] + sbo[1][tid] + sbo[2][tid] + sbo[3][tid];
            g_part4[((size_t)tok * 4 + cg) * 64 + tid] = s;
        }
    }
    float* Sf = out + OUT_OFF;
    size_t base = (((size_t)b * 16 + c) * 64 + i) * 64;
#pragma unroll
    for (int j = 0; j < 64; j++) Sf[base + j] = S[j];
}

// ---------------- K4: reduce over 4 groups -> outputs ------------------------
__global__ void k_reduce(float* __restrict__ out) {
    int idx = blockIdx.x * 256 + threadIdx.x;
    int tok = idx >> 6, i = idx & 63;
    float s = (g_part4[((size_t)tok * 4 + 0) * 64 + i] + g_part4[((size_t)tok * 4 + 1) * 64 + i])
            + (g_part4[((size_t)tok * 4 + 2) * 64 + i] + g_part4[((size_t)tok * 4 + 3) * 64 + i]);
    out[idx] = s;
}

// ---------------- launch -----------------------------------------------------
extern "C" void kernel_launch(void* const* d_in, const int* in_sizes, int n_in,
                              void* d_out, int out_size) {
    const float* x    = (const float*)d_in[0];
    const float* Wr   = (const float*)d_in[1];
    const float* Wkv  = (const float*)d_in[2];
    const float* Wb   = (const float*)d_in[3];
    const float* bb   = (const float*)d_in[4];
    const float* Wq   = (const float*)d_in[5];
    float* out = (float*)d_out;
    (void)in_sizes; (void)n_in; (void)out_size;

    const int prep_grid = NBK * 192 + (NLIST + 255) / 256;   // 3584
    k_prep<<<prep_grid, 256>>>(Wkv, Wb);
    k_rq_mma<<<TOKN / 64, 256>>>(x, Wr, Wq);
    k_ggemm<<<NBK * (CAP / 64), 256>>>(x);
    k_scan<<<BB * 4, 256>>>(bb, out);
    k_reduce<<<(TOKN * 64) / 256, 256>>>(out);
}

// round 11
// speedup vs baseline: 1.4590x; 1.4590x over previous
#include <cuda_runtime.h>
#include <cuda_bf16.h>
#include <math.h>
#include <stdint.h>

#define TT   512
#define BB   64
#define DD   1024
#define NBK  16
#define TOKN (TT*BB)                 // 32768
#define CAP  8192
#define NLIST (NBK*CAP)
#define OUT_OFF ((size_t)TOKN*64)
#define NKTI (DD/16)                 // 64 k-stages of 16

// ---------------- scratch ---------------------------------------------------
__device__ float    g_q[(size_t)TOKN*64];
__device__ float    g_w[TOKN*NBK];
__device__ int      g_sel[TOKN*2];
__device__ float    g_selout[(size_t)TOKN*2*192];
__device__ float    g_partial[(size_t)TOKN*NBK*64];  // 134 MB
__device__ unsigned g_list[NLIST];
__device__ int      g_cursor[NBK];
// W prepack (12.6 MB): unit (row R, kti, j) = (h_b0, h_b1, l_b0, l_b1)
__device__ uint4    g_wpack[(size_t)NBK*192*256];

// ---------------- fast math --------------------------------------------------
__device__ __forceinline__ float ex2a(float x){ float r; asm("ex2.approx.f32 %0,%1;":"=f"(r):"f"(x)); return r; }
__device__ __forceinline__ float rcpa(float x){ float r; asm("rcp.approx.f32 %0,%1;":"=f"(r):"f"(x)); return r; }
__device__ __forceinline__ float fast_rcp(float z){ float y = rcpa(z); return y * fmaf(-z, y, 2.0f); }
__device__ __forceinline__ float fsig(float x){ float E = ex2a(-1.44269504f * x); return fast_rcp(1.0f + E); }
__device__ __forceinline__ float ftanh(float x){ float E = ex2a(2.88539008f * x); return fmaf(-2.0f, fast_rcp(1.0f + E), 1.0f); }

__device__ __forceinline__ uint32_t f2tf(float f){ uint32_t r; asm("cvt.rna.tf32.f32 %0,%1;":"=r"(r):"f"(f)); return r; }
__device__ __forceinline__ uint32_t bf16r(float f){ uint16_t r; asm("cvt.rn.bf16.f32 %0,%1;":"=h"(r):"f"(f)); return (uint32_t)r; }
__device__ __forceinline__ void split_pack(float a, float b, uint32_t &hi, uint32_t &lo){
    uint32_t ha = bf16r(a), hb = bf16r(b);
    float ra = a - __uint_as_float(ha << 16);
    float rb = b - __uint_as_float(hb << 16);
    hi = ha | (hb << 16);
    lo = bf16r(ra) | (bf16r(rb) << 16);
}

__device__ __forceinline__ void mma_tf32(float4 &d, const uint4 &a, const uint2 &b){
    asm volatile("mma.sync.aligned.m16n8k8.row.col.f32.tf32.tf32.f32 "
                 "{%0,%1,%2,%3},{%4,%5,%6,%7},{%8,%9},{%0,%1,%2,%3};"
                 : "+f"(d.x), "+f"(d.y), "+f"(d.z), "+f"(d.w)
                 : "r"(a.x), "r"(a.y), "r"(a.z), "r"(a.w), "r"(b.x), "r"(b.y));
}
__device__ __forceinline__ void mma_bf16(float4 &d, uint32_t a0, uint32_t a1, uint32_t a2, uint32_t a3,
                                         uint32_t b0, uint32_t b1){
    asm volatile("mma.sync.aligned.m16n8k16.row.col.f32.bf16.bf16.f32 "
                 "{%0,%1,%2,%3},{%4,%5,%6,%7},{%8,%9},{%0,%1,%2,%3};"
                 : "+f"(d.x), "+f"(d.y), "+f"(d.z), "+f"(d.w)
                 : "r"(a0), "r"(a1), "r"(a2), "r"(a3), "r"(b0), "r"(b1));
}

__device__ __forceinline__ void cpa16(uint32_t dst, const void* src){
    asm volatile("cp.async.cg.shared.global [%0], [%1], 16;\n" :: "r"(dst), "l"(src));
}
__device__ __forceinline__ void cpa_commit(){ asm volatile("cp.async.commit_group;\n"); }
template<int N> __device__ __forceinline__ void cpa_wait(){ asm volatile("cp.async.wait_group %0;\n"::"n"(N)); }

// ---------------- K0: prep — W split-pack + list init ------------------------
__global__ __launch_bounds__(256) void k_prep(const float* __restrict__ Wkv,
                                              const float* __restrict__ Wbeta) {
    const int bid = blockIdx.x, tid = threadIdx.x;
    if (bid < NBK * 192) {
        const int kti = tid >> 2, j = tid & 3;
        int e = bid / 192, n = bid % 192;
        const float* base = (n < 128) ? (Wkv + ((size_t)e * 128 + n) * DD)
                                      : (Wbeta + ((size_t)e * 64 + (n - 128)) * DD);
        const float* src = base + kti * 16 + 2 * j;
        float2 v0 = *(const float2*)src;
        float2 v1 = *(const float2*)(src + 8);
        uint32_t h0, l0, h1, l1;
        split_pack(v0.x, v0.y, h0, l0);
        split_pack(v1.x, v1.y, h1, l1);
        g_wpack[(size_t)bid * 256 + tid] = make_uint4(h0, h1, l0, l1);
    } else {
        int i = (bid - NBK * 192) * 256 + tid;
        if (i < NLIST) g_list[i] = 0xFFFFFFFFu;
        if (i < NBK)   g_cursor[i] = i * CAP;
    }
}

// ---------------- K1: router+q GEMM (tf32 3-split) + fused top-k/fill --------
__global__ __launch_bounds__(256) void k_rq_mma(const float* __restrict__ x,
                                                const float* __restrict__ Wr,
                                                const float* __restrict__ Wq) {
    __shared__ uint32_t Ah[4*2*32*4], Al[4*2*32*4];
    __shared__ uint32_t Bh[10*2*32*2], Bl[10*2*32*2];
    __shared__ float slog[64][20];

    const int tid = threadIdx.x;
    const int row0 = blockIdx.x * 64;
    const int warp = tid >> 5, lane = tid & 31;
    const int wm = warp >> 1, wn = warp & 1;

    float4 acc[5];
#pragma unroll
    for (int j = 0; j < 5; j++) acc[j] = make_float4(0.f, 0.f, 0.f, 0.f);

    const int xrow = tid >> 2, xk0 = (tid & 3) * 4;
    const float* xp = x + (size_t)(row0 + xrow) * DD + xk0;
    const int xs = xk0 >> 3;
    const int xreg = ((xk0 & 4) ? 2 : 0) + (((xrow & 15) >= 8) ? 1 : 0);
    const int xbase = ((((xrow >> 4) * 2 + xs) * 32 + ((xrow & 7) << 2)) << 2) + xreg;

    for (int kt = 0; kt < DD; kt += 16) {
        {
            float4 v = *(const float4*)(xp + kt);
            float vv[4] = {v.x, v.y, v.z, v.w};
#pragma unroll
            for (int j = 0; j < 4; j++) {
                uint32_t h = f2tf(vv[j]);
                Ah[xbase + (j << 2)] = h;
                Al[xbase + (j << 2)] = f2tf(vv[j] - __uint_as_float(h));
            }
        }
#pragma unroll
        for (int it = 0; it < 2; it++) {
            int fi = tid + it * 256;
            if (fi < 320) {
                int row = fi >> 2, k0 = (fi & 3) * 4;
                const float* wp = (row < 16) ? (Wr + (size_t)row * DD)
                                             : (Wq + (size_t)(row - 16) * DD);
                float4 v = *(const float4*)(wp + kt + k0);
                int s = k0 >> 3, reg = (k0 & 4) ? 1 : 0;
                int base = ((((row >> 3) * 2 + s) * 32 + ((row & 7) << 2)) << 1) + reg;
                float vv[4] = {v.x, v.y, v.z, v.w};
#pragma unroll
                for (int j = 0; j < 4; j++) {
                    uint32_t h = f2tf(vv[j]);
                    Bh[base + (j << 1)] = h;
                    Bl[base + (j << 1)] = f2tf(vv[j] - __uint_as_float(h));
                }
            }
        }
        __syncthreads();
#pragma unroll
        for (int s = 0; s < 2; s++) {
            int aidx = (((wm * 2 + s) * 32 + lane) << 2);
            uint4 ah = *(const uint4*)&Ah[aidx];
            uint4 al = *(const uint4*)&Al[aidx];
#pragma unroll
            for (int ni = 0; ni < 5; ni++) {
                int bidx = ((((wn * 5 + ni) * 2 + s) * 32 + lane) << 1);
                uint2 bh = *(const uint2*)&Bh[bidx];
                uint2 bl = *(const uint2*)&Bl[bidx];
                mma_tf32(acc[ni], ah, bh);
                mma_tf32(acc[ni], ah, bl);
                mma_tf32(acc[ni], al, bh);
            }
        }
        __syncthreads();
    }
    // epilogue: logits -> smem, q -> global
    int rloc = wm * 16 + (lane >> 2);
    int r0 = row0 + rloc;
#pragma unroll
    for (int ni = 0; ni < 5; ni++) {
        int c0 = wn * 40 + ni * 8 + ((lane & 3) << 1);
        if (c0 < 16) {
            slog[rloc][c0]     = acc[ni].x; slog[rloc][c0 + 1]     = acc[ni].y;
            slog[rloc + 8][c0] = acc[ni].z; slog[rloc + 8][c0 + 1] = acc[ni].w;
        } else {
            int c = c0 - 16;
            *(float2*)&g_q[(size_t)r0 * 64 + c]       = make_float2(acc[ni].x, acc[ni].y);
            *(float2*)&g_q[(size_t)(r0 + 8) * 64 + c] = make_float2(acc[ni].z, acc[ni].w);
        }
    }
    __syncthreads();
    if (tid < 64) {
        int tok = row0 + tid;
        float lg[16];
#pragma unroll
        for (int c = 0; c < 16; c++) lg[c] = slog[tid][c];
        float v0 = -1e30f, v1 = -1e30f; int i0 = 0, i1 = 0;
#pragma unroll
        for (int c = 0; c < 16; c++) {
            float l = lg[c];
            if (l > v0) { v1 = v0; i1 = i0; v0 = l; i0 = c; }
            else if (l > v1) { v1 = l; i1 = c; }
        }
        float s = 0.0f, w[16];
#pragma unroll
        for (int c = 0; c < 16; c++) { float e = __expf(lg[c] - v0); w[c] = e; s += e; }
        float rs = 1.0f / s;
#pragma unroll
        for (int c = 0; c < 16; c++) g_w[(size_t)tok * 16 + c] = w[c] * rs;
        g_sel[tok * 2 + 0] = i0;
        g_sel[tok * 2 + 1] = i1;
        int p0 = atomicAdd(&g_cursor[i0], 1); g_list[p0] = (unsigned)(tok * 2);
        int p1 = atomicAdd(&g_cursor[i1], 1); g_list[p1] = (unsigned)(tok * 2 + 1);
    }
}

// ---------------- K2: grouped bf16 3-split GEMM (R6 layout, unchanged) -------
__global__ __launch_bounds__(256, 2) void k_ggemm(const float* __restrict__ x) {
    __shared__ __align__(16) uint4 SMA[2][4 * 2 * 32];
    __shared__ __align__(16) uint4 SMB[2][24 * 32];
    __shared__ unsigned s_ent[64];

    const int tid = threadIdx.x;
    const int e = blockIdx.x >> 7;
    const int lofs = e * CAP + (blockIdx.x & 127) * 64;
    if (tid < 64) s_ent[tid] = g_list[lofs + tid];
    __syncthreads();
    if (s_ent[0] == 0xFFFFFFFFu) return;

    const int warp = tid >> 5, lane = tid & 31;
    const int wm = warp >> 2, wn = warp & 3;

    const int a_mt = tid >> 6, a_rlow = (tid >> 3) & 7, a_j = tid & 7;
    const int a_lane = a_rlow * 4 + (a_j & 3);
    const int a_reg  = (a_j >= 4) ? 2 : 0;
    const float* a_p0;
    const float* a_p1;
    {
        unsigned e0 = s_ent[a_mt * 16 + a_rlow];
        unsigned e1 = s_ent[a_mt * 16 + a_rlow + 8];
        a_p0 = (e0 != 0xFFFFFFFFu) ? (x + (size_t)(e0 >> 1) * DD + 2 * a_j) : nullptr;
        a_p1 = (e1 != 0xFFFFFFFFu) ? (x + (size_t)(e1 >> 1) * DD + 2 * a_j) : nullptr;
    }
    uint32_t a_hi_addr = (uint32_t)__cvta_generic_to_shared(
        &((uint32_t*)&SMA[0][(a_mt * 2 + 0) * 32 + a_lane])[a_reg]);
    uint32_t a_lo_addr = (uint32_t)__cvta_generic_to_shared(
        &((uint32_t*)&SMA[0][(a_mt * 2 + 1) * 32 + a_lane])[a_reg]);

    const uint4* b_src[3];
    uint32_t b_dst[3];
#pragma unroll
    for (int i = 0; i < 3; i++) {
        int u = tid + i * 256;
        int n = u >> 2, j = u & 3;
        b_src[i] = &g_wpack[((size_t)e * 192 + n) * 256 + j];
        b_dst[i] = (uint32_t)__cvta_generic_to_shared(&SMB[0][(n >> 3) * 32 + (n & 7) * 4 + j]);
    }

    float4 acc[2][6];
#pragma unroll
    for (int i = 0; i < 2; i++)
#pragma unroll
        for (int j = 0; j < 6; j++) acc[i][j] = make_float4(0.f, 0.f, 0.f, 0.f);

    {
        float2 v0 = make_float2(0.f, 0.f), v1 = v0;
        if (a_p0) v0 = *(const float2*)a_p0;
        if (a_p1) v1 = *(const float2*)a_p1;
        uint32_t h0, l0, h1, l1;
        split_pack(v0.x, v0.y, h0, l0);
        split_pack(v1.x, v1.y, h1, l1);
        asm volatile("st.shared.v2.u32 [%0], {%1,%2};" :: "r"(a_hi_addr), "r"(h0), "r"(h1));
        asm volatile("st.shared.v2.u32 [%0], {%1,%2};" :: "r"(a_lo_addr), "r"(l0), "r"(l1));
#pragma unroll
        for (int i = 0; i < 3; i++) cpa16(b_dst[i], b_src[i]);
        cpa_commit();
    }

    const uint32_t ABUF = sizeof(uint4) * 4 * 2 * 32;
    const uint32_t BBUF = sizeof(uint4) * 24 * 32;

    for (int kts = 0; kts < NKTI; kts++) {
        const int buf = kts & 1;
        float2 va0 = make_float2(0.f, 0.f), va1 = va0;
        const bool more = (kts + 1 < NKTI);
        if (more) {
            if (a_p0) va0 = *(const float2*)(a_p0 + (kts + 1) * 16);
            if (a_p1) va1 = *(const float2*)(a_p1 + (kts + 1) * 16);
        }
        cpa_wait<0>();
        __syncthreads();
        if (more) {
            uint32_t bo = (buf ^ 1) * BBUF;
#pragma unroll
            for (int i = 0; i < 3; i++) cpa16(b_dst[i] + bo, b_src[i] + (size_t)(kts + 1) * 4);
            cpa_commit();
        }
        {
            const uint4* A0 = SMA[buf];
            const uint4* B0 = SMB[buf];
            uint4 qa_h[2], qa_l[2];
#pragma unroll
            for (int mi = 0; mi < 2; mi++) {
                int mt = wm * 2 + mi;
                qa_h[mi] = A0[(mt * 2 + 0) * 32 + lane];
                qa_l[mi] = A0[(mt * 2 + 1) * 32 + lane];
            }
#pragma unroll
            for (int ni = 0; ni < 6; ni++) {
                uint4 qb = B0[(wn * 6 + ni) * 32 + lane];
#pragma unroll
                for (int mi = 0; mi < 2; mi++) {
                    float4 &d = acc[mi][ni];
                    mma_bf16(d, qa_h[mi].x, qa_h[mi].y, qa_h[mi].z, qa_h[mi].w, qb.x, qb.y);
                    mma_bf16(d, qa_h[mi].x, qa_h[mi].y, qa_h[mi].z, qa_h[mi].w, qb.z, qb.w);
                    mma_bf16(d, qa_l[mi].x, qa_l[mi].y, qa_l[mi].z, qa_l[mi].w, qb.x, qb.y);
                }
            }
        }
        if (more) {
            uint32_t h0, l0, h1, l1;
            split_pack(va0.x, va0.y, h0, l0);
            split_pack(va1.x, va1.y, h1, l1);
            uint32_t ao = (buf ^ 1) * ABUF;
            asm volatile("st.shared.v2.u32 [%0], {%1,%2};" :: "r"(a_hi_addr + ao), "r"(h0), "r"(h1));
            asm volatile("st.shared.v2.u32 [%0], {%1,%2};" :: "r"(a_lo_addr + ao), "r"(l0), "r"(l1));
        }
    }

#pragma unroll
    for (int mi = 0; mi < 2; mi++) {
        int r0 = (wm * 2 + mi) * 16 + (lane >> 2);
        unsigned e0 = s_ent[r0], e1 = s_ent[r0 + 8];
#pragma unroll
        for (int ni = 0; ni < 6; ni++) {
            int c0 = wn * 48 + ni * 8 + ((lane & 3) << 1);
            if (e0 != 0xFFFFFFFFu)
                *(float2*)&g_selout[(size_t)e0 * 192 + c0] = make_float2(acc[mi][ni].x, acc[mi][ni].y);
            if (e1 != 0xFFFFFFFFu)
                *(float2*)&g_selout[(size_t)e1 * 192 + c0] = make_float2(acc[mi][ni].z, acc[mi][ni].w);
        }
    }
}

// ---------------- K3: recurrent scan — R4 verbatim (1024 CTAs x 64 thr) ------
__global__ __launch_bounds__(64) void k_scan(const float* __restrict__ b_beta,
                                             float* __restrict__ out) {
    const int bc = blockIdx.x;
    const int b = bc >> 4, c = bc & 15;
    const int tid = threadIdx.x;

    float S[64];
#pragma unroll
    for (int j = 0; j < 64; j++) S[j] = 0.0f;
    const float bb = b_beta[c * 64 + tid];

    __shared__ float sq[2][64];
    __shared__ float sk[64];
    __shared__ float spart[2];
    __shared__ int   ssel[2][2];
    __shared__ float sww[2];

    for (int t = 0; t < TT; t++) {
        const int tok = t * BB + b;
        const int p = t & 1;
        sq[p][tid] = g_q[(size_t)tok * 64 + tid];
        if (tid == 0) {
            ssel[p][0] = g_sel[tok * 2 + 0];
            ssel[p][1] = g_sel[tok * 2 + 1];
            sww[p] = g_w[(size_t)tok * 16 + c];
        }
        __syncthreads();
        const int slot = (ssel[p][0] == c) ? 0 : ((ssel[p][1] == c) ? 1 : -1);
        if (slot >= 0) {   // CTA-uniform
            const float* sel = g_selout + ((size_t)tok * 2 + slot) * 192;
            float kk = sel[tid], vv = sel[64 + tid], bp = sel[128 + tid];
            float ps = kk * kk;
#pragma unroll
            for (int o = 16; o; o >>= 1) ps += __shfl_xor_sync(0xffffffffu, ps, o);
            if ((tid & 31) == 0) spart[tid >> 5] = ps;
            __syncthreads();
            float rn = 1.0f / (sqrtf(spart[0] + spart[1]) + 1e-6f);
            sk[tid] = kk * rn;
            __syncthreads();
            float r0 = 0.f, r1 = 0.f, r2 = 0.f, r3 = 0.f;
#pragma unroll
            for (int j = 0; j < 64; j += 4) {
                r0 = fmaf(S[j+0], sk[j+0], r0);
                r1 = fmaf(S[j+1], sk[j+1], r1);
                r2 = fmaf(S[j+2], sk[j+2], r2);
                r3 = fmaf(S[j+3], sk[j+3], r3);
            }
            float delta = vv - ((r0 + r1) + (r2 + r3));
            float beta = fsig(bp + bb);
#pragma unroll
            for (int j = 0; j < 64; j++)
                S[j] = ftanh(fmaf(beta, S[j], delta * sk[j]));
        }
        float a0 = 0.f, a1 = 0.f, a2 = 0.f, a3 = 0.f;
        const float* q = sq[p];
#pragma unroll
        for (int j = 0; j < 64; j += 4) {
            a0 = fmaf(S[j+0], q[j+0], a0);
            a1 = fmaf(S[j+1], q[j+1], a1);
            a2 = fmaf(S[j+2], q[j+2], a2);
            a3 = fmaf(S[j+3], q[j+3], a3);
        }
        float sv = (a0 + a1) + (a2 + a3);
        g_partial[((size_t)tok * 16 + c) * 64 + tid] = sww[p] * sv * sv * fsig(sv);
    }
    float* Sf = out + OUT_OFF;
    size_t base = (((size_t)b * 16 + c) * 64 + tid) * 64;
#pragma unroll
    for (int j = 0; j < 64; j++) Sf[base + j] = S[j];
}

// ---------------- K4: reduce over blocks -> outputs --------------------------
__global__ void k_reduce(float* __restrict__ out) {
    int idx = blockIdx.x * 256 + threadIdx.x;
    int tok = idx >> 6, i = idx & 63;
    float s = 0.0f;
#pragma unroll
    for (int c = 0; c < 16; c++)
        s += g_partial[((size_t)tok * 16 + c) * 64 + i];
    out[idx] = s;
}

// ---------------- launch -----------------------------------------------------
extern "C" void kernel_launch(void* const* d_in, const int* in_sizes, int n_in,
                              void* d_out, int out_size) {
    const float* x    = (const float*)d_in[0];
    const float* Wr   = (const float*)d_in[1];
    const float* Wkv  = (const float*)d_in[2];
    const float* Wb   = (const float*)d_in[3];
    const float* bb   = (const float*)d_in[4];
    const float* Wq   = (const float*)d_in[5];
    float* out = (float*)d_out;
    (void)in_sizes; (void)n_in; (void)out_size;

    const int prep_grid = NBK * 192 + (NLIST + 255) / 256;   // 3584
    k_prep<<<prep_grid, 256>>>(Wkv, Wb);
    k_rq_mma<<<TOKN / 64, 256>>>(x, Wr, Wq);
    k_ggemm<<<NBK * (CAP / 64), 256>>>(x);
    k_scan<<<BB * NBK, 64>>>(bb, out);
    k_reduce<<<(TOKN * 64) / 256, 256>>>(out);
}

// round 12
// speedup vs baseline: 1.6599x; 1.1377x over previous
#include <cuda_runtime.h>
#include <cuda_bf16.h>
#include <math.h>
#include <stdint.h>

#define TT   512
#define BB   64
#define DD   1024
#define NBK  16
#define TOKN (TT*BB)                 // 32768
#define CAP  8192
#define NLIST (NBK*CAP)
#define OUT_OFF ((size_t)TOKN*64)
#define NKTI (DD/16)                 // 64 k-stages of 16

// ---------------- scratch ---------------------------------------------------
__device__ float    g_q[(size_t)TOKN*64];
__device__ float    g_w[TOKN*NBK];
__device__ int      g_sel[TOKN*2];
__device__ float    g_selout[(size_t)TOKN*2*192];
__device__ float    g_partial[(size_t)TOKN*NBK*64];  // 134 MB
__device__ unsigned g_list[NLIST];
__device__ int      g_cursor[NBK];
// W prepack (12.6 MB): unit (row R, kti, j) = (h_b0, h_b1, l_b0, l_b1)
__device__ uint4    g_wpack[(size_t)NBK*192*256];

// ---------------- fast math --------------------------------------------------
__device__ __forceinline__ float ex2a(float x){ float r; asm("ex2.approx.f32 %0,%1;":"=f"(r):"f"(x)); return r; }
__device__ __forceinline__ float rcpa(float x){ float r; asm("rcp.approx.f32 %0,%1;":"=f"(r):"f"(x)); return r; }
__device__ __forceinline__ float fast_rcp(float z){ float y = rcpa(z); return y * fmaf(-z, y, 2.0f); }
__device__ __forceinline__ float fsig(float x){ float E = ex2a(-1.44269504f * x); return fast_rcp(1.0f + E); }
__device__ __forceinline__ float ftanh(float x){ float E = ex2a(2.88539008f * x); return fmaf(-2.0f, fast_rcp(1.0f + E), 1.0f); }

__device__ __forceinline__ uint32_t f2tf(float f){ uint32_t r; asm("cvt.rna.tf32.f32 %0,%1;":"=r"(r):"f"(f)); return r; }
__device__ __forceinline__ uint32_t bf16r(float f){ uint16_t r; asm("cvt.rn.bf16.f32 %0,%1;":"=h"(r):"f"(f)); return (uint32_t)r; }
__device__ __forceinline__ void split_pack(float a, float b, uint32_t &hi, uint32_t &lo){
    uint32_t ha = bf16r(a), hb = bf16r(b);
    float ra = a - __uint_as_float(ha << 16);
    float rb = b - __uint_as_float(hb << 16);
    hi = ha | (hb << 16);
    lo = bf16r(ra) | (bf16r(rb) << 16);
}

__device__ __forceinline__ void mma_tf32(float4 &d, const uint4 &a, const uint2 &b){
    asm volatile("mma.sync.aligned.m16n8k8.row.col.f32.tf32.tf32.f32 "
                 "{%0,%1,%2,%3},{%4,%5,%6,%7},{%8,%9},{%0,%1,%2,%3};"
                 : "+f"(d.x), "+f"(d.y), "+f"(d.z), "+f"(d.w)
                 : "r"(a.x), "r"(a.y), "r"(a.z), "r"(a.w), "r"(b.x), "r"(b.y));
}
__device__ __forceinline__ void mma_bf16(float4 &d, uint32_t a0, uint32_t a1, uint32_t a2, uint32_t a3,
                                         uint32_t b0, uint32_t b1){
    asm volatile("mma.sync.aligned.m16n8k16.row.col.f32.bf16.bf16.f32 "
                 "{%0,%1,%2,%3},{%4,%5,%6,%7},{%8,%9},{%0,%1,%2,%3};"
                 : "+f"(d.x), "+f"(d.y), "+f"(d.z), "+f"(d.w)
                 : "r"(a0), "r"(a1), "r"(a2), "r"(a3), "r"(b0), "r"(b1));
}

__device__ __forceinline__ void cpa16(uint32_t dst, const void* src){
    asm volatile("cp.async.cg.shared.global [%0], [%1], 16;\n" :: "r"(dst), "l"(src));
}
__device__ __forceinline__ void cpa_commit(){ asm volatile("cp.async.commit_group;\n"); }
template<int N> __device__ __forceinline__ void cpa_wait(){ asm volatile("cp.async.wait_group %0;\n"::"n"(N)); }

// ---------------- K0: prep — W split-pack + list init ------------------------
__global__ __launch_bounds__(256) void k_prep(const float* __restrict__ Wkv,
                                              const float* __restrict__ Wbeta) {
    const int bid = blockIdx.x, tid = threadIdx.x;
    if (bid < NBK * 192) {
        const int kti = tid >> 2, j = tid & 3;
        int e = bid / 192, n = bid % 192;
        const float* base = (n < 128) ? (Wkv + ((size_t)e * 128 + n) * DD)
                                      : (Wbeta + ((size_t)e * 64 + (n - 128)) * DD);
        const float* src = base + kti * 16 + 2 * j;
        float2 v0 = *(const float2*)src;
        float2 v1 = *(const float2*)(src + 8);
        uint32_t h0, l0, h1, l1;
        split_pack(v0.x, v0.y, h0, l0);
        split_pack(v1.x, v1.y, h1, l1);
        g_wpack[(size_t)bid * 256 + tid] = make_uint4(h0, h1, l0, l1);
    } else {
        int i = (bid - NBK * 192) * 256 + tid;
        if (i < NLIST) g_list[i] = 0xFFFFFFFFu;
        if (i < NBK)   g_cursor[i] = i * CAP;
    }
}

// ---------------- K1: router+q GEMM (tf32 3-split) + fused top-k/fill --------
__global__ __launch_bounds__(256) void k_rq_mma(const float* __restrict__ x,
                                                const float* __restrict__ Wr,
                                                const float* __restrict__ Wq) {
    __shared__ uint32_t Ah[4*2*32*4], Al[4*2*32*4];
    __shared__ uint32_t Bh[10*2*32*2], Bl[10*2*32*2];
    __shared__ float slog[64][20];

    const int tid = threadIdx.x;
    const int row0 = blockIdx.x * 64;
    const int warp = tid >> 5, lane = tid & 31;
    const int wm = warp >> 1, wn = warp & 1;

    float4 acc[5];
#pragma unroll
    for (int j = 0; j < 5; j++) acc[j] = make_float4(0.f, 0.f, 0.f, 0.f);

    const int xrow = tid >> 2, xk0 = (tid & 3) * 4;
    const float* xp = x + (size_t)(row0 + xrow) * DD + xk0;
    const int xs = xk0 >> 3;
    const int xreg = ((xk0 & 4) ? 2 : 0) + (((xrow & 15) >= 8) ? 1 : 0);
    const int xbase = ((((xrow >> 4) * 2 + xs) * 32 + ((xrow & 7) << 2)) << 2) + xreg;

    for (int kt = 0; kt < DD; kt += 16) {
        {
            float4 v = *(const float4*)(xp + kt);
            float vv[4] = {v.x, v.y, v.z, v.w};
#pragma unroll
            for (int j = 0; j < 4; j++) {
                uint32_t h = f2tf(vv[j]);
                Ah[xbase + (j << 2)] = h;
                Al[xbase + (j << 2)] = f2tf(vv[j] - __uint_as_float(h));
            }
        }
#pragma unroll
        for (int it = 0; it < 2; it++) {
            int fi = tid + it * 256;
            if (fi < 320) {
                int row = fi >> 2, k0 = (fi & 3) * 4;
                const float* wp = (row < 16) ? (Wr + (size_t)row * DD)
                                             : (Wq + (size_t)(row - 16) * DD);
                float4 v = *(const float4*)(wp + kt + k0);
                int s = k0 >> 3, reg = (k0 & 4) ? 1 : 0;
                int base = ((((row >> 3) * 2 + s) * 32 + ((row & 7) << 2)) << 1) + reg;
                float vv[4] = {v.x, v.y, v.z, v.w};
#pragma unroll
                for (int j = 0; j < 4; j++) {
                    uint32_t h = f2tf(vv[j]);
                    Bh[base + (j << 1)] = h;
                    Bl[base + (j << 1)] = f2tf(vv[j] - __uint_as_float(h));
                }
            }
        }
        __syncthreads();
#pragma unroll
        for (int s = 0; s < 2; s++) {
            int aidx = (((wm * 2 + s) * 32 + lane) << 2);
            uint4 ah = *(const uint4*)&Ah[aidx];
            uint4 al = *(const uint4*)&Al[aidx];
#pragma unroll
            for (int ni = 0; ni < 5; ni++) {
                int bidx = ((((wn * 5 + ni) * 2 + s) * 32 + lane) << 1);
                uint2 bh = *(const uint2*)&Bh[bidx];
                uint2 bl = *(const uint2*)&Bl[bidx];
                mma_tf32(acc[ni], ah, bh);
                mma_tf32(acc[ni], ah, bl);
                mma_tf32(acc[ni], al, bh);
            }
        }
        __syncthreads();
    }
    int rloc = wm * 16 + (lane >> 2);
    int r0 = row0 + rloc;
#pragma unroll
    for (int ni = 0; ni < 5; ni++) {
        int c0 = wn * 40 + ni * 8 + ((lane & 3) << 1);
        if (c0 < 16) {
            slog[rloc][c0]     = acc[ni].x; slog[rloc][c0 + 1]     = acc[ni].y;
            slog[rloc + 8][c0] = acc[ni].z; slog[rloc + 8][c0 + 1] = acc[ni].w;
        } else {
            int c = c0 - 16;
            *(float2*)&g_q[(size_t)r0 * 64 + c]       = make_float2(acc[ni].x, acc[ni].y);
            *(float2*)&g_q[(size_t)(r0 + 8) * 64 + c] = make_float2(acc[ni].z, acc[ni].w);
        }
    }
    __syncthreads();
    if (tid < 64) {
        int tok = row0 + tid;
        float lg[16];
#pragma unroll
        for (int c = 0; c < 16; c++) lg[c] = slog[tid][c];
        float v0 = -1e30f, v1 = -1e30f; int i0 = 0, i1 = 0;
#pragma unroll
        for (int c = 0; c < 16; c++) {
            float l = lg[c];
            if (l > v0) { v1 = v0; i1 = i0; v0 = l; i0 = c; }
            else if (l > v1) { v1 = l; i1 = c; }
        }
        float s = 0.0f, w[16];
#pragma unroll
        for (int c = 0; c < 16; c++) { float e = __expf(lg[c] - v0); w[c] = e; s += e; }
        float rs = 1.0f / s;
#pragma unroll
        for (int c = 0; c < 16; c++) g_w[(size_t)tok * 16 + c] = w[c] * rs;
        g_sel[tok * 2 + 0] = i0;
        g_sel[tok * 2 + 1] = i1;
        int p0 = atomicAdd(&g_cursor[i0], 1); g_list[p0] = (unsigned)(tok * 2);
        int p1 = atomicAdd(&g_cursor[i1], 1); g_list[p1] = (unsigned)(tok * 2 + 1);
    }
}

// ---------------- K2: grouped bf16 3-split GEMM (unchanged) ------------------
__global__ __launch_bounds__(256, 2) void k_ggemm(const float* __restrict__ x) {
    __shared__ __align__(16) uint4 SMA[2][4 * 2 * 32];
    __shared__ __align__(16) uint4 SMB[2][24 * 32];
    __shared__ unsigned s_ent[64];

    const int tid = threadIdx.x;
    const int e = blockIdx.x >> 7;
    const int lofs = e * CAP + (blockIdx.x & 127) * 64;
    if (tid < 64) s_ent[tid] = g_list[lofs + tid];
    __syncthreads();
    if (s_ent[0] == 0xFFFFFFFFu) return;

    const int warp = tid >> 5, lane = tid & 31;
    const int wm = warp >> 2, wn = warp & 3;

    const int a_mt = tid >> 6, a_rlow = (tid >> 3) & 7, a_j = tid & 7;
    const int a_lane = a_rlow * 4 + (a_j & 3);
    const int a_reg  = (a_j >= 4) ? 2 : 0;
    const float* a_p0;
    const float* a_p1;
    {
        unsigned e0 = s_ent[a_mt * 16 + a_rlow];
        unsigned e1 = s_ent[a_mt * 16 + a_rlow + 8];
        a_p0 = (e0 != 0xFFFFFFFFu) ? (x + (size_t)(e0 >> 1) * DD + 2 * a_j) : nullptr;
        a_p1 = (e1 != 0xFFFFFFFFu) ? (x + (size_t)(e1 >> 1) * DD + 2 * a_j) : nullptr;
    }
    uint32_t a_hi_addr = (uint32_t)__cvta_generic_to_shared(
        &((uint32_t*)&SMA[0][(a_mt * 2 + 0) * 32 + a_lane])[a_reg]);
    uint32_t a_lo_addr = (uint32_t)__cvta_generic_to_shared(
        &((uint32_t*)&SMA[0][(a_mt * 2 + 1) * 32 + a_lane])[a_reg]);

    const uint4* b_src[3];
    uint32_t b_dst[3];
#pragma unroll
    for (int i = 0; i < 3; i++) {
        int u = tid + i * 256;
        int n = u >> 2, j = u & 3;
        b_src[i] = &g_wpack[((size_t)e * 192 + n) * 256 + j];
        b_dst[i] = (uint32_t)__cvta_generic_to_shared(&SMB[0][(n >> 3) * 32 + (n & 7) * 4 + j]);
    }

    float4 acc[2][6];
#pragma unroll
    for (int i = 0; i < 2; i++)
#pragma unroll
        for (int j = 0; j < 6; j++) acc[i][j] = make_float4(0.f, 0.f, 0.f, 0.f);

    {
        float2 v0 = make_float2(0.f, 0.f), v1 = v0;
        if (a_p0) v0 = *(const float2*)a_p0;
        if (a_p1) v1 = *(const float2*)a_p1;
        uint32_t h0, l0, h1, l1;
        split_pack(v0.x, v0.y, h0, l0);
        split_pack(v1.x, v1.y, h1, l1);
        asm volatile("st.shared.v2.u32 [%0], {%1,%2};" :: "r"(a_hi_addr), "r"(h0), "r"(h1));
        asm volatile("st.shared.v2.u32 [%0], {%1,%2};" :: "r"(a_lo_addr), "r"(l0), "r"(l1));
#pragma unroll
        for (int i = 0; i < 3; i++) cpa16(b_dst[i], b_src[i]);
        cpa_commit();
    }

    const uint32_t ABUF = sizeof(uint4) * 4 * 2 * 32;
    const uint32_t BBUF = sizeof(uint4) * 24 * 32;

    for (int kts = 0; kts < NKTI; kts++) {
        const int buf = kts & 1;
        float2 va0 = make_float2(0.f, 0.f), va1 = va0;
        const bool more = (kts + 1 < NKTI);
        if (more) {
            if (a_p0) va0 = *(const float2*)(a_p0 + (kts + 1) * 16);
            if (a_p1) va1 = *(const float2*)(a_p1 + (kts + 1) * 16);
        }
        cpa_wait<0>();
        __syncthreads();
        if (more) {
            uint32_t bo = (buf ^ 1) * BBUF;
#pragma unroll
            for (int i = 0; i < 3; i++) cpa16(b_dst[i] + bo, b_src[i] + (size_t)(kts + 1) * 4);
            cpa_commit();
        }
        {
            const uint4* A0 = SMA[buf];
            const uint4* B0 = SMB[buf];
            uint4 qa_h[2], qa_l[2];
#pragma unroll
            for (int mi = 0; mi < 2; mi++) {
                int mt = wm * 2 + mi;
                qa_h[mi] = A0[(mt * 2 + 0) * 32 + lane];
                qa_l[mi] = A0[(mt * 2 + 1) * 32 + lane];
            }
#pragma unroll
            for (int ni = 0; ni < 6; ni++) {
                uint4 qb = B0[(wn * 6 + ni) * 32 + lane];
#pragma unroll
                for (int mi = 0; mi < 2; mi++) {
                    float4 &d = acc[mi][ni];
                    mma_bf16(d, qa_h[mi].x, qa_h[mi].y, qa_h[mi].z, qa_h[mi].w, qb.x, qb.y);
                    mma_bf16(d, qa_h[mi].x, qa_h[mi].y, qa_h[mi].z, qa_h[mi].w, qb.z, qb.w);
                    mma_bf16(d, qa_l[mi].x, qa_l[mi].y, qa_l[mi].z, qa_l[mi].w, qb.x, qb.y);
                }
            }
        }
        if (more) {
            uint32_t h0, l0, h1, l1;
            split_pack(va0.x, va0.y, h0, l0);
            split_pack(va1.x, va1.y, h1, l1);
            uint32_t ao = (buf ^ 1) * ABUF;
            asm volatile("st.shared.v2.u32 [%0], {%1,%2};" :: "r"(a_hi_addr + ao), "r"(h0), "r"(h1));
            asm volatile("st.shared.v2.u32 [%0], {%1,%2};" :: "r"(a_lo_addr + ao), "r"(l0), "r"(l1));
        }
    }

#pragma unroll
    for (int mi = 0; mi < 2; mi++) {
        int r0 = (wm * 2 + mi) * 16 + (lane >> 2);
        unsigned e0 = s_ent[r0], e1 = s_ent[r0 + 8];
#pragma unroll
        for (int ni = 0; ni < 6; ni++) {
            int c0 = wn * 48 + ni * 8 + ((lane & 3) << 1);
            if (e0 != 0xFFFFFFFFu)
                *(float2*)&g_selout[(size_t)e0 * 192 + c0] = make_float2(acc[mi][ni].x, acc[mi][ni].y);
            if (e1 != 0xFFFFFFFFu)
                *(float2*)&g_selout[(size_t)e1 * 192 + c0] = make_float2(acc[mi][ni].z, acc[mi][ni].w);
        }
    }
}

// ---------------- K3: recurrent scan v4 --------------------------------------
// 1024 CTAs x 64 thr; 8 CTAs/SM via launch_bounds; float4 LDS; raw-k norm fold;
// double-buffered sq+sk -> exactly 1 barrier per step.
__global__ __launch_bounds__(64, 8) void k_scan(const float* __restrict__ b_beta,
                                                float* __restrict__ out) {
    const int bc = blockIdx.x;
    const int b = bc >> 4, c = bc & 15;
    const int tid = threadIdx.x;

    float4 S[16];
#pragma unroll
    for (int j = 0; j < 16; j++) S[j] = make_float4(0.f, 0.f, 0.f, 0.f);
    const float bb = b_beta[c * 64 + tid];

    __shared__ __align__(16) float sq[2][64];
    __shared__ __align__(16) float sk[2][64];

    for (int t = 0; t < TT; t++) {
        const int tok = t * BB + b;
        const int p = t & 1;
        const float qv = g_q[(size_t)tok * 64 + tid];
        const int2 sel = *(const int2*)&g_sel[tok * 2];
        const float wv = g_w[(size_t)tok * 16 + c];
        const int slot = (sel.x == c) ? 0 : ((sel.y == c) ? 1 : -1);
        float kk = 0.f, vv = 0.f, bp = 0.f;
        if (slot >= 0) {
            const float* pp = g_selout + ((size_t)tok * 2 + slot) * 192;
            kk = pp[tid]; vv = pp[64 + tid]; bp = pp[128 + tid];
        }
        sq[p][tid] = qv;
        sk[p][tid] = kk;
        __syncthreads();                       // one barrier per step

        if (slot >= 0) {                       // CTA-uniform
            float k1 = sk[p][tid ^ 32];
            float ps = fmaf(kk, kk, k1 * k1);
#pragma unroll
            for (int o = 16; o; o >>= 1) ps += __shfl_xor_sync(0xffffffffu, ps, o);
            float rn = fast_rcp(sqrtf(ps) + 1e-6f);
            const float4* k4 = (const float4*)sk[p];
            float r0 = 0.f, r1 = 0.f, r2 = 0.f, r3 = 0.f;
#pragma unroll
            for (int j = 0; j < 16; j++) {
                float4 kq = k4[j];
                r0 = fmaf(S[j].x, kq.x, r0);
                r1 = fmaf(S[j].y, kq.y, r1);
                r2 = fmaf(S[j].z, kq.z, r2);
                r3 = fmaf(S[j].w, kq.w, r3);
            }
            float delta = vv - ((r0 + r1) + (r2 + r3)) * rn;
            float beta = fsig(bp + bb);
            float sc = delta * rn;
#pragma unroll 8
            for (int j = 0; j < 16; j++) {
                float4 kq = k4[j];
                S[j].x = ftanh(fmaf(beta, S[j].x, sc * kq.x));
                S[j].y = ftanh(fmaf(beta, S[j].y, sc * kq.y));
                S[j].z = ftanh(fmaf(beta, S[j].z, sc * kq.z));
                S[j].w = ftanh(fmaf(beta, S[j].w, sc * kq.w));
            }
        }
        const float4* q4 = (const float4*)sq[p];
        float a0 = 0.f, a1 = 0.f, a2 = 0.f, a3 = 0.f;
#pragma unroll
        for (int j = 0; j < 16; j++) {
            float4 qq = q4[j];
            a0 = fmaf(S[j].x, qq.x, a0);
            a1 = fmaf(S[j].y, qq.y, a1);
            a2 = fmaf(S[j].z, qq.z, a2);
            a3 = fmaf(S[j].w, qq.w, a3);
        }
        float sv = (a0 + a1) + (a2 + a3);
        g_partial[((size_t)tok * 16 + c) * 64 + tid] = wv * sv * sv * fsig(sv);
    }
    float* Sf = out + OUT_OFF;
    size_t base = (((size_t)b * 16 + c) * 64 + tid) * 64;
#pragma unroll
    for (int j = 0; j < 16; j++) *(float4*)&Sf[base + j * 4] = S[j];
}

// ---------------- K4: reduce over blocks -> outputs --------------------------
__global__ void k_reduce(float* __restrict__ out) {
    int idx = blockIdx.x * 256 + threadIdx.x;
    int tok = idx >> 6, i = idx & 63;
    float s = 0.0f;
#pragma unroll
    for (int c = 0; c < 16; c++)
        s += g_partial[((size_t)tok * 16 + c) * 64 + i];
    out[idx] = s;
}

// ---------------- launch -----------------------------------------------------
extern "C" void kernel_launch(void* const* d_in, const int* in_sizes, int n_in,
                              void* d_out, int out_size) {
    const float* x    = (const float*)d_in[0];
    const float* Wr   = (const float*)d_in[1];
    const float* Wkv  = (const float*)d_in[2];
    const float* Wb   = (const float*)d_in[3];
    const float* bb   = (const float*)d_in[4];
    const float* Wq   = (const float*)d_in[5];
    float* out = (float*)d_out;
    (void)in_sizes; (void)n_in; (void)out_size;

    const int prep_grid = NBK * 192 + (NLIST + 255) / 256;   // 3584
    k_prep<<<prep_grid, 256>>>(Wkv, Wb);
    k_rq_mma<<<TOKN / 64, 256>>>(x, Wr, Wq);
    k_ggemm<<<NBK * (CAP / 64), 256>>>(x);
    k_scan<<<BB * NBK, 64>>>(bb, out);
    k_reduce<<<(TOKN * 64) / 256, 256>>>(out);
}